// round 7
// baseline (speedup 1.0000x reference)
#include <cuda_runtime.h>
#include <cuda_bf16.h>
#include <cstdint>

// Problem constants
#define VOCABN 50257
#define SMALLN 512
#define LARGEN 1024
#define NTOK   8192      // B*S = 4*2048

// bf16 staging buffers (device globals: allocation-free scratch)
__device__ __nv_bfloat16 g_Abf[NTOK * SMALLN];    // gathered weight rows, bf16
__device__ __nv_bfloat16 g_Bbf[SMALLN * SMALLN];  // cw, bf16

// ---------------------------------------------------------------------------
// Kernel 1 (slim prep): stage bf16 gathered weight rows + bf16 cw.
// Unit = 8 elements (one 16B bf16 store).
// ---------------------------------------------------------------------------
#define A_UNITS (NTOK * 64)              // 524288
#define B_UNITS (SMALLN * 64)            // 32768
#define PREP_UNITS (A_UNITS + B_UNITS)

__global__ void prepA_kernel(const int* __restrict__ ids,
                             const float4* __restrict__ w4,     // [VOCAB][128]
                             const float4* __restrict__ cw4) {  // [512][128]
    int u = blockIdx.x * blockDim.x + threadIdx.x;
    float4 v0, v1;
    uint4* dst;
    if (u < A_UNITS) {
        int t = u >> 6;
        int c8 = u & 63;                 // 8-elem chunk
        int id = ids[t];
        v0 = w4[(size_t)id * 128 + c8 * 2];
        v1 = w4[(size_t)id * 128 + c8 * 2 + 1];
        dst = reinterpret_cast<uint4*>(g_Abf + (size_t)t * SMALLN + c8 * 8);
    } else {
        int i = u - A_UNITS;             // 0..32767
        v0 = cw4[(size_t)i * 2];
        v1 = cw4[(size_t)i * 2 + 1];
        dst = reinterpret_cast<uint4*>(g_Bbf + (size_t)i * 8);
    }
    __nv_bfloat162 p0 = {__float2bfloat16(v0.x), __float2bfloat16(v0.y)};
    __nv_bfloat162 p1 = {__float2bfloat16(v0.z), __float2bfloat16(v0.w)};
    __nv_bfloat162 p2 = {__float2bfloat16(v1.x), __float2bfloat16(v1.y)};
    __nv_bfloat162 p3 = {__float2bfloat16(v1.z), __float2bfloat16(v1.w)};
    uint4 pack;
    pack.x = *reinterpret_cast<uint32_t*>(&p0);
    pack.y = *reinterpret_cast<uint32_t*>(&p1);
    pack.z = *reinterpret_cast<uint32_t*>(&p2);
    pack.w = *reinterpret_cast<uint32_t*>(&p3);
    *dst = pack;
}

// ---------------------------------------------------------------------------
// Kernel 2: GEMM second half + FUSED first-half gather+add + residual epilogue
// 3-stage cp.async pipelined bf16 mma.sync GEMM with ldmatrix.
// BM=256, BN=128, BK=64, 512 threads (16 warps 4x4), warp tile 64x32.
// Grid (4, 32) = 128 CTAs = one wave.
// ---------------------------------------------------------------------------
#define BM 256
#define BN 128
#define BK 64
#define KP 72
#define STAGES 3
#define ASZ (BM * KP)
#define BSZ (BN * KP)
#define STAGE_ELEMS (ASZ + BSZ)
#define SMEM_BYTES (STAGES * STAGE_ELEMS * 2)   // 165,888 B

__device__ __forceinline__ void cpa16(void* sm, const void* g) {
    uint32_t s = (uint32_t)__cvta_generic_to_shared(sm);
    asm volatile("cp.async.cg.shared.global [%0], [%1], 16;\n" :: "r"(s), "l"(g));
}
__device__ __forceinline__ void ldsm_x4(uint32_t& d0, uint32_t& d1,
                                        uint32_t& d2, uint32_t& d3, uint32_t a) {
    asm volatile("ldmatrix.sync.aligned.m8n8.x4.shared.b16 {%0,%1,%2,%3}, [%4];"
                 : "=r"(d0), "=r"(d1), "=r"(d2), "=r"(d3) : "r"(a));
}
__device__ __forceinline__ void prefetchL2(const void* p) {
    asm volatile("prefetch.global.L2 [%0];" :: "l"(p));
}

__global__ __launch_bounds__(512, 1)
void gemm_fused(const int* __restrict__ ids,
                const float* __restrict__ weight,     // [VOCAB][512]
                const float* __restrict__ residual,   // [VOCAB][1024]
                float* __restrict__ out) {            // [NTOK][1024]
    extern __shared__ __nv_bfloat16 smem[];
    __shared__ int sids[BM];

    const int bn = blockIdx.x;        // 0..3
    const int bm = blockIdx.y;        // 0..31
    const int tid  = threadIdx.x;
    const int warp = tid >> 5;
    const int lane = tid & 31;
    const int wm = warp >> 2;         // 0..3
    const int wn = warp & 3;          // 0..3
    const int g  = lane >> 2;
    const int tg = lane & 3;

    if (tid < BM) sids[tid] = ids[bm * BM + tid];

    const uint32_t smem_b = (uint32_t)__cvta_generic_to_shared(smem);
    const uint32_t a_off = (uint32_t)(((lane & 15) * KP + ((lane >> 4) << 3)) * 2);
    const uint32_t b_off = (uint32_t)((((lane & 7) + ((lane >> 4) << 3)) * KP +
                                      (((lane >> 3) & 1) << 3)) * 2);

    auto load_stage = [&](int s, int kt) {
        __nv_bfloat16* As = smem + s * STAGE_ELEMS;
        __nv_bfloat16* Bs = As + ASZ;
        #pragma unroll
        for (int i = 0; i < 4; i++) {
            int c   = tid + i * 512;
            int row = c >> 3;
            int kc  = (c & 7) * 8;
            cpa16(As + row * KP + kc,
                  g_Abf + (size_t)(bm * BM + row) * SMALLN + kt + kc);
        }
        #pragma unroll
        for (int i = 0; i < 2; i++) {
            int c   = tid + i * 512;
            int row = c >> 3;
            int kc  = (c & 7) * 8;
            cpa16(Bs + row * KP + kc,
                  g_Bbf + (size_t)(bn * BN + row) * SMALLN + kt + kc);
        }
    };

    float acc[4][4][4];
    #pragma unroll
    for (int mi = 0; mi < 4; mi++)
        #pragma unroll
        for (int ni = 0; ni < 4; ni++)
            #pragma unroll
            for (int r = 0; r < 4; r++) acc[mi][ni][r] = 0.f;

    // ---- prologue ----
    load_stage(0, 0);
    asm volatile("cp.async.commit_group;\n");
    load_stage(1, BK);
    asm volatile("cp.async.commit_group;\n");
    __syncthreads();   // sids visible (fused first-half + prefetch need it)

    // L2 prefetch of epilogue residual rows (second half, this CTA's slab)
    {
        #pragma unroll
        for (int i = 0; i < 2; i++) {
            int u = tid * 2 + i;           // 0..1023
            int row = u >> 2;              // 0..255
            int ln  = u & 3;
            prefetchL2(residual + (size_t)sids[row] * LARGEN + SMALLN +
                       bn * BN + ln * 32);
        }
    }

    // Per-thread fused-copy unit schedule: units tid + k*512, k = 0..15
    // unit -> row = u>>5, col4 = u&31. Precompute first pair's ids.
    #pragma unroll 1
    for (int kt8 = 0; kt8 < 8; kt8++) {
        asm volatile("cp.async.wait_group 1;\n");
        __syncthreads();

        if (kt8 + 2 < 8) load_stage((kt8 + 2) % STAGES, (kt8 + 2) * BK);
        asm volatile("cp.async.commit_group;\n");

        // --- fused first-half: issue LDGs early (consumed after MMAs) ---
        int u0 = tid + (kt8 * 2    ) * 512;        // 0..8191
        int u1 = tid + (kt8 * 2 + 1) * 512;
        int fr0 = u0 >> 5, fc0 = u0 & 31;
        int fr1 = u1 >> 5, fc1 = u1 & 31;
        int fid0 = sids[fr0];
        int fid1 = sids[fr1];
        float4 w0 = *reinterpret_cast<const float4*>(
            weight + (size_t)fid0 * SMALLN + bn * BN + fc0 * 4);
        float4 r0 = *reinterpret_cast<const float4*>(
            residual + (size_t)fid0 * LARGEN + bn * BN + fc0 * 4);
        float4 w1 = *reinterpret_cast<const float4*>(
            weight + (size_t)fid1 * SMALLN + bn * BN + fc1 * 4);
        float4 r1 = *reinterpret_cast<const float4*>(
            residual + (size_t)fid1 * LARGEN + bn * BN + fc1 * 4);

        const uint32_t As = smem_b + (uint32_t)((kt8 % STAGES) * STAGE_ELEMS) * 2;
        const uint32_t Bs = As + ASZ * 2;

        #pragma unroll
        for (int kh = 0; kh < 4; kh++) {
            const int kk = kh * 16;
            uint32_t af[4][4], bf[4][2];
            #pragma unroll
            for (int mi = 0; mi < 4; mi++) {
                int r0i = wm * 64 + mi * 16;
                ldsm_x4(af[mi][0], af[mi][1], af[mi][2], af[mi][3],
                        As + a_off + (uint32_t)((r0i * KP + kk) * 2));
            }
            #pragma unroll
            for (int nb = 0; nb < 2; nb++) {
                int n0 = wn * 32 + nb * 16;
                ldsm_x4(bf[nb * 2][0], bf[nb * 2][1],
                        bf[nb * 2 + 1][0], bf[nb * 2 + 1][1],
                        Bs + b_off + (uint32_t)((n0 * KP + kk) * 2));
            }
            #pragma unroll
            for (int mi = 0; mi < 4; mi++)
                #pragma unroll
                for (int ni = 0; ni < 4; ni++) {
                    asm volatile(
                        "mma.sync.aligned.m16n8k16.row.col.f32.bf16.bf16.f32 "
                        "{%0,%1,%2,%3}, {%4,%5,%6,%7}, {%8,%9}, {%0,%1,%2,%3};\n"
                        : "+f"(acc[mi][ni][0]), "+f"(acc[mi][ni][1]),
                          "+f"(acc[mi][ni][2]), "+f"(acc[mi][ni][3])
                        : "r"(af[mi][0]), "r"(af[mi][1]), "r"(af[mi][2]), "r"(af[mi][3]),
                          "r"(bf[ni][0]), "r"(bf[ni][1]));
                }
        }

        // --- fused first-half: combine + store (LDG latency hidden) ---
        {
            float4 o0, o1;
            o0.x = w0.x + r0.x; o0.y = w0.y + r0.y;
            o0.z = w0.z + r0.z; o0.w = w0.w + r0.w;
            o1.x = w1.x + r1.x; o1.y = w1.y + r1.y;
            o1.z = w1.z + r1.z; o1.w = w1.w + r1.w;
            *reinterpret_cast<float4*>(
                out + (size_t)(bm * BM + fr0) * LARGEN + bn * BN + fc0 * 4) = o0;
            *reinterpret_cast<float4*>(
                out + (size_t)(bm * BM + fr1) * LARGEN + bn * BN + fc1 * 4) = o1;
        }
    }

    // ---- epilogue: + residual[id, 512+col] -> out[t, 512+col] ----
    #pragma unroll
    for (int mi = 0; mi < 4; mi++) {
        const int lr0 = wm * 64 + mi * 16 + g;
        const int t0  = bm * BM + lr0;
        const int id0 = sids[lr0];
        const int id1 = sids[lr0 + 8];
        #pragma unroll
        for (int ni = 0; ni < 4; ni++) {
            const int col = bn * BN + wn * 32 + ni * 8 + tg * 2;
            {
                float2 rv = *reinterpret_cast<const float2*>(
                    residual + (size_t)id0 * LARGEN + SMALLN + col);
                float2 o;
                o.x = acc[mi][ni][0] + rv.x;
                o.y = acc[mi][ni][1] + rv.y;
                *reinterpret_cast<float2*>(
                    out + (size_t)t0 * LARGEN + SMALLN + col) = o;
            }
            {
                float2 rv = *reinterpret_cast<const float2*>(
                    residual + (size_t)id1 * LARGEN + SMALLN + col);
                float2 o;
                o.x = acc[mi][ni][2] + rv.x;
                o.y = acc[mi][ni][3] + rv.y;
                *reinterpret_cast<float2*>(
                    out + (size_t)(t0 + 8) * LARGEN + SMALLN + col) = o;
            }
        }
    }
}

// ---------------------------------------------------------------------------
// Launch
// ---------------------------------------------------------------------------
extern "C" void kernel_launch(void* const* d_in, const int* in_sizes, int n_in,
                              void* d_out, int out_size) {
    const int*   ids      = (const int*)  d_in[0];  // [4,2048]
    const float* weight   = (const float*)d_in[1];  // [50257,512]
    const float* cw       = (const float*)d_in[2];  // [512,512]
    const float* residual = (const float*)d_in[3];  // [50257,1024]
    float* out = (float*)d_out;                     // [8192,1024]

    cudaFuncSetAttribute(gemm_fused,
                         cudaFuncAttributeMaxDynamicSharedMemorySize, SMEM_BYTES);

    // slim prep: Abf + Bbf staging only
    prepA_kernel<<<PREP_UNITS / 256, 256>>>(
        ids,
        reinterpret_cast<const float4*>(weight),
        reinterpret_cast<const float4*>(cw));

    // fused GEMM: second half + first half + epilogue (one wave: 128 CTAs)
    {
        dim3 grid(SMALLN / BN, NTOK / BM);          // (4, 32)
        gemm_fused<<<grid, 512, SMEM_BYTES>>>(ids, weight, residual, out);
    }
}

// round 8
// speedup vs baseline: 1.0202x; 1.0202x over previous
#include <cuda_runtime.h>
#include <cuda_bf16.h>
#include <cstdint>

// Problem constants
#define VOCABN 50257
#define SMALLN 512
#define LARGEN 1024
#define NTOK   8192      // B*S = 4*2048

// bf16 staging buffers (device globals: allocation-free scratch)
__device__ __nv_bfloat16 g_Abf[NTOK * SMALLN];    // gathered weight rows, bf16
__device__ __nv_bfloat16 g_Bbf[SMALLN * SMALLN];  // cw, bf16

// ---------------------------------------------------------------------------
// Kernel 1 (merged prep): first-half gather+add, A bf16 staging, cw bf16
// (identical to the proven R5 prep)
// ---------------------------------------------------------------------------
#define GATHER_UNITS (NTOK * 128)
#define CW_UNITS     (SMALLN * SMALLN / 4)

__global__ void prep_kernel(const int* __restrict__ ids,
                            const float4* __restrict__ w4,
                            const float4* __restrict__ r4,
                            const float4* __restrict__ cw4,
                            float4* __restrict__ out4) {
    int gid = blockIdx.x * blockDim.x + threadIdx.x;
    if (gid < GATHER_UNITS) {
        int t = gid >> 7;
        int c = gid & 127;
        int id = ids[t];
        float4 a = w4[(size_t)id * 128 + c];
        float4 b = r4[(size_t)id * 256 + c];
        float4 o;
        o.x = a.x + b.x; o.y = a.y + b.y; o.z = a.z + b.z; o.w = a.w + b.w;
        out4[(size_t)t * 256 + c] = o;

        __nv_bfloat162 p0 = {__float2bfloat16(a.x), __float2bfloat16(a.y)};
        __nv_bfloat162 p1 = {__float2bfloat16(a.z), __float2bfloat16(a.w)};
        __nv_bfloat162* ap = reinterpret_cast<__nv_bfloat162*>(
            g_Abf + (size_t)t * SMALLN + c * 4);
        ap[0] = p0;
        ap[1] = p1;
    } else {
        int i = gid - GATHER_UNITS;
        float4 v = cw4[i];
        __nv_bfloat162 p0 = {__float2bfloat16(v.x), __float2bfloat16(v.y)};
        __nv_bfloat162 p1 = {__float2bfloat16(v.z), __float2bfloat16(v.w)};
        __nv_bfloat162* bp = reinterpret_cast<__nv_bfloat162*>(g_Bbf + (size_t)i * 4);
        bp[0] = p0;
        bp[1] = p1;
    }
}

// ---------------------------------------------------------------------------
// Kernel 2: C[8192,512] = Abf @ Bbf^T (+ residual gather epilogue)
// 3-stage cp.async pipelined bf16 mma.sync GEMM with ldmatrix.
// BM=128, BN=128, BK=64, 256 threads (8 warps 2x4), warp tile 64x32.
// Grid (4, 64) = 256 CTAs; __launch_bounds__(256,2) -> 2 CTAs/SM resident
// (221 KB smem of 228, <=128 regs) so barrier stalls overlap across CTAs.
// ---------------------------------------------------------------------------
#define BM 128
#define BN 128
#define BK 64
#define KP 72                       // padded smem row stride (bf16); 144B
#define STAGES 3
#define ASZ (BM * KP)
#define BSZ (BN * KP)
#define STAGE_ELEMS (ASZ + BSZ)
#define SMEM_BYTES (STAGES * STAGE_ELEMS * 2)   // 110,592 B

__device__ __forceinline__ void cpa16(void* sm, const void* g) {
    uint32_t s = (uint32_t)__cvta_generic_to_shared(sm);
    asm volatile("cp.async.cg.shared.global [%0], [%1], 16;\n" :: "r"(s), "l"(g));
}
__device__ __forceinline__ void ldsm_x4(uint32_t& d0, uint32_t& d1,
                                        uint32_t& d2, uint32_t& d3, uint32_t a) {
    asm volatile("ldmatrix.sync.aligned.m8n8.x4.shared.b16 {%0,%1,%2,%3}, [%4];"
                 : "=r"(d0), "=r"(d1), "=r"(d2), "=r"(d3) : "r"(a));
}

__global__ __launch_bounds__(256, 2)
void gemm_second_half(const int* __restrict__ ids,
                      const float* __restrict__ residual,   // [VOCAB][1024]
                      float* __restrict__ out) {            // [NTOK][1024]
    extern __shared__ __nv_bfloat16 smem[];
    __shared__ int sids[BM];

    const int bn = blockIdx.x;        // 0..3
    const int bm = blockIdx.y;        // 0..63
    const int tid  = threadIdx.x;
    const int warp = tid >> 5;
    const int lane = tid & 31;
    const int wm = warp >> 2;         // 0..1  (64-row slab)
    const int wn = warp & 3;          // 0..3  (32-col slab)
    const int g  = lane >> 2;         // 0..7
    const int tg = lane & 3;          // 0..3

    if (tid < BM) sids[tid] = ids[bm * BM + tid];

    const uint32_t smem_b = (uint32_t)__cvta_generic_to_shared(smem);
    // ldmatrix per-lane offsets (bytes) relative to fragment origin
    const uint32_t a_off = (uint32_t)(((lane & 15) * KP + ((lane >> 4) << 3)) * 2);
    const uint32_t b_off = (uint32_t)((((lane & 7) + ((lane >> 4) << 3)) * KP +
                                      (((lane >> 3) & 1) << 3)) * 2);

    // ---- stage loader: A 128x64 + B 128x64 bf16, 16B cp.async chunks ----
    auto load_stage = [&](int s, int kt) {
        __nv_bfloat16* As = smem + s * STAGE_ELEMS;
        __nv_bfloat16* Bs = As + ASZ;
        #pragma unroll
        for (int i = 0; i < 4; i++) {                // A: 1024 chunks
            int c   = tid + i * 256;
            int row = c >> 3;
            int kc  = (c & 7) * 8;
            cpa16(As + row * KP + kc,
                  g_Abf + (size_t)(bm * BM + row) * SMALLN + kt + kc);
        }
        #pragma unroll
        for (int i = 0; i < 4; i++) {                // B: 1024 chunks
            int c   = tid + i * 256;
            int row = c >> 3;
            int kc  = (c & 7) * 8;
            cpa16(Bs + row * KP + kc,
                  g_Bbf + (size_t)(bn * BN + row) * SMALLN + kt + kc);
        }
    };

    float acc[4][4][4];
    #pragma unroll
    for (int mi = 0; mi < 4; mi++)
        #pragma unroll
        for (int ni = 0; ni < 4; ni++)
            #pragma unroll
            for (int r = 0; r < 4; r++) acc[mi][ni][r] = 0.f;

    // ---- prologue: fill 2 stages ----
    load_stage(0, 0);
    asm volatile("cp.async.commit_group;\n");
    load_stage(1, BK);
    asm volatile("cp.async.commit_group;\n");

    // ---- mainloop: 8 K-tiles ----
    #pragma unroll 1
    for (int kt8 = 0; kt8 < 8; kt8++) {
        asm volatile("cp.async.wait_group 1;\n");
        __syncthreads();

        if (kt8 + 2 < 8) load_stage((kt8 + 2) % STAGES, (kt8 + 2) * BK);
        asm volatile("cp.async.commit_group;\n");

        const uint32_t As = smem_b + (uint32_t)((kt8 % STAGES) * STAGE_ELEMS) * 2;
        const uint32_t Bs = As + ASZ * 2;

        #pragma unroll
        for (int kh = 0; kh < 4; kh++) {
            const int kk = kh * 16;
            uint32_t af[4][4], bf[4][2];
            #pragma unroll
            for (int mi = 0; mi < 4; mi++) {
                int r0i = wm * 64 + mi * 16;
                ldsm_x4(af[mi][0], af[mi][1], af[mi][2], af[mi][3],
                        As + a_off + (uint32_t)((r0i * KP + kk) * 2));
            }
            #pragma unroll
            for (int nb = 0; nb < 2; nb++) {
                int n0 = wn * 32 + nb * 16;
                ldsm_x4(bf[nb * 2][0], bf[nb * 2][1],
                        bf[nb * 2 + 1][0], bf[nb * 2 + 1][1],
                        Bs + b_off + (uint32_t)((n0 * KP + kk) * 2));
            }
            #pragma unroll
            for (int mi = 0; mi < 4; mi++)
                #pragma unroll
                for (int ni = 0; ni < 4; ni++) {
                    asm volatile(
                        "mma.sync.aligned.m16n8k16.row.col.f32.bf16.bf16.f32 "
                        "{%0,%1,%2,%3}, {%4,%5,%6,%7}, {%8,%9}, {%0,%1,%2,%3};\n"
                        : "+f"(acc[mi][ni][0]), "+f"(acc[mi][ni][1]),
                          "+f"(acc[mi][ni][2]), "+f"(acc[mi][ni][3])
                        : "r"(af[mi][0]), "r"(af[mi][1]), "r"(af[mi][2]), "r"(af[mi][3]),
                          "r"(bf[ni][0]), "r"(bf[ni][1]));
                }
        }
    }

    // ---- epilogue: + residual[id, 512+col] -> out[t, 512+col] ----
    #pragma unroll
    for (int mi = 0; mi < 4; mi++) {
        const int lr0 = wm * 64 + mi * 16 + g;
        const int t0  = bm * BM + lr0;
        const int id0 = sids[lr0];
        const int id1 = sids[lr0 + 8];
        #pragma unroll
        for (int ni = 0; ni < 4; ni++) {
            const int col = bn * BN + wn * 32 + ni * 8 + tg * 2;
            {
                float2 rv = *reinterpret_cast<const float2*>(
                    residual + (size_t)id0 * LARGEN + SMALLN + col);
                float2 o;
                o.x = acc[mi][ni][0] + rv.x;
                o.y = acc[mi][ni][1] + rv.y;
                *reinterpret_cast<float2*>(
                    out + (size_t)t0 * LARGEN + SMALLN + col) = o;
            }
            {
                float2 rv = *reinterpret_cast<const float2*>(
                    residual + (size_t)id1 * LARGEN + SMALLN + col);
                float2 o;
                o.x = acc[mi][ni][2] + rv.x;
                o.y = acc[mi][ni][3] + rv.y;
                *reinterpret_cast<float2*>(
                    out + (size_t)(t0 + 8) * LARGEN + SMALLN + col) = o;
            }
        }
    }
}

// ---------------------------------------------------------------------------
// Launch
// ---------------------------------------------------------------------------
extern "C" void kernel_launch(void* const* d_in, const int* in_sizes, int n_in,
                              void* d_out, int out_size) {
    const int*   ids      = (const int*)  d_in[0];  // [4,2048]
    const float* weight   = (const float*)d_in[1];  // [50257,512]
    const float* cw       = (const float*)d_in[2];  // [512,512]
    const float* residual = (const float*)d_in[3];  // [50257,1024]
    float* out = (float*)d_out;                     // [8192,1024]

    cudaFuncSetAttribute(gemm_second_half,
                         cudaFuncAttributeMaxDynamicSharedMemorySize, SMEM_BYTES);

    // merged prep: gather+add first half, stage Abf, convert cw
    {
        int total = GATHER_UNITS + CW_UNITS;        // 1,114,112
        prep_kernel<<<total / 256, 256>>>(
            ids,
            reinterpret_cast<const float4*>(weight),
            reinterpret_cast<const float4*>(residual),
            reinterpret_cast<const float4*>(cw),
            reinterpret_cast<float4*>(out));
    }

    // pipelined GEMM + residual epilogue (256 CTAs, 2 resident per SM)
    {
        dim3 grid(SMALLN / BN, NTOK / BM);          // (4, 64)
        gemm_second_half<<<grid, 256, SMEM_BYTES>>>(ids, residual, out);
    }
}

// round 9
// speedup vs baseline: 1.1311x; 1.1087x over previous
#include <cuda_runtime.h>
#include <cuda_bf16.h>
#include <cstdint>

// Problem constants
#define VOCABN 50257
#define SMALLN 512
#define LARGEN 1024
#define NTOK   8192      // B*S = 4*2048

// bf16 staging buffers (device globals: allocation-free scratch)
__device__ __nv_bfloat16 g_Abf[NTOK * SMALLN];    // gathered weight rows, bf16
__device__ __nv_bfloat16 g_Bbf[SMALLN * SMALLN];  // cw, bf16

// ---------------------------------------------------------------------------
// Kernel 1 (merged prep): first-half gather+add, A bf16 staging, cw bf16
// (identical to the proven R5 prep)
// ---------------------------------------------------------------------------
#define GATHER_UNITS (NTOK * 128)
#define CW_UNITS     (SMALLN * SMALLN / 4)

__global__ void prep_kernel(const int* __restrict__ ids,
                            const float4* __restrict__ w4,
                            const float4* __restrict__ r4,
                            const float4* __restrict__ cw4,
                            float4* __restrict__ out4) {
    int gid = blockIdx.x * blockDim.x + threadIdx.x;
    if (gid < GATHER_UNITS) {
        int t = gid >> 7;
        int c = gid & 127;
        int id = ids[t];
        float4 a = w4[(size_t)id * 128 + c];
        float4 b = r4[(size_t)id * 256 + c];
        float4 o;
        o.x = a.x + b.x; o.y = a.y + b.y; o.z = a.z + b.z; o.w = a.w + b.w;
        out4[(size_t)t * 256 + c] = o;

        __nv_bfloat162 p0 = {__float2bfloat16(a.x), __float2bfloat16(a.y)};
        __nv_bfloat162 p1 = {__float2bfloat16(a.z), __float2bfloat16(a.w)};
        __nv_bfloat162* ap = reinterpret_cast<__nv_bfloat162*>(
            g_Abf + (size_t)t * SMALLN + c * 4);
        ap[0] = p0;
        ap[1] = p1;
    } else {
        int i = gid - GATHER_UNITS;
        float4 v = cw4[i];
        __nv_bfloat162 p0 = {__float2bfloat16(v.x), __float2bfloat16(v.y)};
        __nv_bfloat162 p1 = {__float2bfloat16(v.z), __float2bfloat16(v.w)};
        __nv_bfloat162* bp = reinterpret_cast<__nv_bfloat162*>(g_Bbf + (size_t)i * 4);
        bp[0] = p0;
        bp[1] = p1;
    }
}

// ---------------------------------------------------------------------------
// Kernel 2: C[8192,512] = Abf @ Bbf^T (+ residual gather epilogue)
// 3-stage cp.async pipelined bf16 mma.sync GEMM, BIG warp tiles (64x64).
// BM=128, BN=256, BK=64, 256 threads (8 warps, 2x4), warp tile 64x64.
// Grid (2, 64) = 128 CTAs = one wave. 256 thr/CTA -> 255-reg budget so
// ptxas can software-pipeline LDSM under HMMA (acc 128 + frags ~48).
// Crossbar fragment traffic per output cut 1.7x vs 64x32 warp tiles.
// ---------------------------------------------------------------------------
#define BM 128
#define BN 256
#define BK 64
#define KP 72                       // padded smem row stride (bf16); 144B
#define STAGES 3
#define ASZ (BM * KP)               // 9216 elems
#define BSZ (BN * KP)               // 18432 elems
#define STAGE_ELEMS (ASZ + BSZ)
#define SMEM_BYTES (STAGES * STAGE_ELEMS * 2)   // 165,888 B

__device__ __forceinline__ void cpa16(void* sm, const void* g) {
    uint32_t s = (uint32_t)__cvta_generic_to_shared(sm);
    asm volatile("cp.async.cg.shared.global [%0], [%1], 16;\n" :: "r"(s), "l"(g));
}
__device__ __forceinline__ void ldsm_x4(uint32_t& d0, uint32_t& d1,
                                        uint32_t& d2, uint32_t& d3, uint32_t a) {
    asm volatile("ldmatrix.sync.aligned.m8n8.x4.shared.b16 {%0,%1,%2,%3}, [%4];"
                 : "=r"(d0), "=r"(d1), "=r"(d2), "=r"(d3) : "r"(a));
}

__global__ __launch_bounds__(256, 1)
void gemm_second_half(const int* __restrict__ ids,
                      const float* __restrict__ residual,   // [VOCAB][1024]
                      float* __restrict__ out) {            // [NTOK][1024]
    extern __shared__ __nv_bfloat16 smem[];
    __shared__ int sids[BM];

    const int bn = blockIdx.x;        // 0..1
    const int bm = blockIdx.y;        // 0..63
    const int tid  = threadIdx.x;
    const int warp = tid >> 5;
    const int lane = tid & 31;
    const int wm = warp >> 2;         // 0..1  (64-row slab)
    const int wn = warp & 3;          // 0..3  (64-col slab)
    const int g  = lane >> 2;         // 0..7
    const int tg = lane & 3;          // 0..3

    if (tid < BM) sids[tid] = ids[bm * BM + tid];

    const uint32_t smem_b = (uint32_t)__cvta_generic_to_shared(smem);
    // ldmatrix per-lane offsets (bytes) relative to fragment origin
    const uint32_t a_off = (uint32_t)(((lane & 15) * KP + ((lane >> 4) << 3)) * 2);
    const uint32_t b_off = (uint32_t)((((lane & 7) + ((lane >> 4) << 3)) * KP +
                                      (((lane >> 3) & 1) << 3)) * 2);

    // ---- stage loader: A 128x64 + B 256x64 bf16, 16B cp.async chunks ----
    auto load_stage = [&](int s, int kt) {
        __nv_bfloat16* As = smem + s * STAGE_ELEMS;
        __nv_bfloat16* Bs = As + ASZ;
        #pragma unroll
        for (int i = 0; i < 4; i++) {                // A: 1024 chunks
            int c   = tid + i * 256;
            int row = c >> 3;
            int kc  = (c & 7) * 8;
            cpa16(As + row * KP + kc,
                  g_Abf + (size_t)(bm * BM + row) * SMALLN + kt + kc);
        }
        #pragma unroll
        for (int i = 0; i < 8; i++) {                // B: 2048 chunks
            int c   = tid + i * 256;
            int row = c >> 3;
            int kc  = (c & 7) * 8;
            cpa16(Bs + row * KP + kc,
                  g_Bbf + (size_t)(bn * BN + row) * SMALLN + kt + kc);
        }
    };

    float acc[4][8][4];
    #pragma unroll
    for (int mi = 0; mi < 4; mi++)
        #pragma unroll
        for (int ni = 0; ni < 8; ni++)
            #pragma unroll
            for (int r = 0; r < 4; r++) acc[mi][ni][r] = 0.f;

    // ---- prologue: fill 2 stages ----
    load_stage(0, 0);
    asm volatile("cp.async.commit_group;\n");
    load_stage(1, BK);
    asm volatile("cp.async.commit_group;\n");

    // ---- mainloop: 8 K-tiles ----
    #pragma unroll 1
    for (int kt8 = 0; kt8 < 8; kt8++) {
        asm volatile("cp.async.wait_group 1;\n");
        __syncthreads();

        if (kt8 + 2 < 8) load_stage((kt8 + 2) % STAGES, (kt8 + 2) * BK);
        asm volatile("cp.async.commit_group;\n");

        const uint32_t As = smem_b + (uint32_t)((kt8 % STAGES) * STAGE_ELEMS) * 2;
        const uint32_t Bs = As + ASZ * 2;

        #pragma unroll
        for (int kh = 0; kh < 4; kh++) {
            const int kk = kh * 16;
            uint32_t af[4][4], bf[8][2];
            // A fragments: 4 x ldmatrix.x4 (64 rows)
            #pragma unroll
            for (int mi = 0; mi < 4; mi++) {
                int r0i = wm * 64 + mi * 16;
                ldsm_x4(af[mi][0], af[mi][1], af[mi][2], af[mi][3],
                        As + a_off + (uint32_t)((r0i * KP + kk) * 2));
            }
            // B fragments: 4 x ldmatrix.x4 (64 cols; each covers 2 ni blocks)
            #pragma unroll
            for (int nb = 0; nb < 4; nb++) {
                int n0 = wn * 64 + nb * 16;
                ldsm_x4(bf[nb * 2][0], bf[nb * 2][1],
                        bf[nb * 2 + 1][0], bf[nb * 2 + 1][1],
                        Bs + b_off + (uint32_t)((n0 * KP + kk) * 2));
            }
            #pragma unroll
            for (int mi = 0; mi < 4; mi++)
                #pragma unroll
                for (int ni = 0; ni < 8; ni++) {
                    asm volatile(
                        "mma.sync.aligned.m16n8k16.row.col.f32.bf16.bf16.f32 "
                        "{%0,%1,%2,%3}, {%4,%5,%6,%7}, {%8,%9}, {%0,%1,%2,%3};\n"
                        : "+f"(acc[mi][ni][0]), "+f"(acc[mi][ni][1]),
                          "+f"(acc[mi][ni][2]), "+f"(acc[mi][ni][3])
                        : "r"(af[mi][0]), "r"(af[mi][1]), "r"(af[mi][2]), "r"(af[mi][3]),
                          "r"(bf[ni][0]), "r"(bf[ni][1]));
                }
        }
    }

    // ---- epilogue: + residual[id, 512+col] -> out[t, 512+col] ----
    #pragma unroll
    for (int mi = 0; mi < 4; mi++) {
        const int lr0 = wm * 64 + mi * 16 + g;
        const int t0  = bm * BM + lr0;
        const int id0 = sids[lr0];
        const int id1 = sids[lr0 + 8];
        #pragma unroll
        for (int ni = 0; ni < 8; ni++) {
            const int col = bn * BN + wn * 64 + ni * 8 + tg * 2;   // 0..511
            {
                float2 rv = *reinterpret_cast<const float2*>(
                    residual + (size_t)id0 * LARGEN + SMALLN + col);
                float2 o;
                o.x = acc[mi][ni][0] + rv.x;
                o.y = acc[mi][ni][1] + rv.y;
                *reinterpret_cast<float2*>(
                    out + (size_t)t0 * LARGEN + SMALLN + col) = o;
            }
            {
                float2 rv = *reinterpret_cast<const float2*>(
                    residual + (size_t)id1 * LARGEN + SMALLN + col);
                float2 o;
                o.x = acc[mi][ni][2] + rv.x;
                o.y = acc[mi][ni][3] + rv.y;
                *reinterpret_cast<float2*>(
                    out + (size_t)(t0 + 8) * LARGEN + SMALLN + col) = o;
            }
        }
    }
}

// ---------------------------------------------------------------------------
// Launch
// ---------------------------------------------------------------------------
extern "C" void kernel_launch(void* const* d_in, const int* in_sizes, int n_in,
                              void* d_out, int out_size) {
    const int*   ids      = (const int*)  d_in[0];  // [4,2048]
    const float* weight   = (const float*)d_in[1];  // [50257,512]
    const float* cw       = (const float*)d_in[2];  // [512,512]
    const float* residual = (const float*)d_in[3];  // [50257,1024]
    float* out = (float*)d_out;                     // [8192,1024]

    cudaFuncSetAttribute(gemm_second_half,
                         cudaFuncAttributeMaxDynamicSharedMemorySize, SMEM_BYTES);

    // merged prep: gather+add first half, stage Abf, convert cw
    {
        int total = GATHER_UNITS + CW_UNITS;        // 1,114,112
        prep_kernel<<<total / 256, 256>>>(
            ids,
            reinterpret_cast<const float4*>(weight),
            reinterpret_cast<const float4*>(residual),
            reinterpret_cast<const float4*>(cw),
            reinterpret_cast<float4*>(out));
    }

    // pipelined GEMM + residual epilogue (one wave: 128 CTAs)
    {
        dim3 grid(SMALLN / BN, NTOK / BM);          // (2, 64)
        gemm_second_half<<<grid, 256, SMEM_BYTES>>>(ids, residual, out);
    }
}